// round 3
// baseline (speedup 1.0000x reference)
#include <cuda_runtime.h>
#include <math.h>

#define Bb 8
#define Nn 2048
#define Kk 20

// ---------------- scratch (static device globals; no allocation) -------------
__device__ float g_pd[(size_t)Bb * Nn * Nn];     // 134 MB distance matrix
__device__ int   g_idx[Bb * Nn * Kk];            // knn indices
__device__ float g_sq[Bb * Nn];                  // squared norms
__device__ float g_h[(size_t)Bb * 256 * Nn];     // concat buffer (max 256 ch)
__device__ float g_att[(size_t)Bb * 128 * Nn];   // attention output (max 128 ch)
__device__ float g_xc[(size_t)Bb * 512 * Nn];    // x1|x2|x3|x4 concat
__device__ float g_x5[(size_t)Bb * 1024 * Nn];   // conv5 output
__device__ float g_mean[1024];
__device__ float g_rstd[1024];
__device__ float g_p[Bb * 2048];
__device__ float g_f1[Bb * 512];
__device__ float g_f2[Bb * 256];

// ---------------- kernels ----------------------------------------------------

// squared norm per point: sq[b*N+n] = sum_c X[b][c][n]^2
__global__ void k_sqnorm(const float* __restrict__ X, long bsx, int C,
                         float* __restrict__ sq) {
    int i = blockIdx.x * blockDim.x + threadIdx.x;
    if (i >= Bb * Nn) return;
    int b = i / Nn, n = i % Nn;
    const float* xp = X + (long)b * bsx + n;
    float s = 0.f;
    for (int c = 0; c < C; c++) { float v = xp[(long)c * Nn]; s += v * v; }
    sq[i] = s;
}

// squared distance matrix: pd[b][n][m] = |x_n|^2 + |x_m|^2 - 2 x_n.x_m ; diag=INF
__global__ void k_dist(const float* __restrict__ X, long bsx, int C,
                       const float* __restrict__ sq, float* __restrict__ pd) {
    int b = blockIdx.z;
    int n0 = blockIdx.y * 32, m0 = blockIdx.x * 32;
    __shared__ float sA[32][33], sB[32][33];
    const float* Xb = X + (long)b * bsx;
    int tx = threadIdx.x, ty = threadIdx.y;   // 16x16
    int t = ty * 16 + tx;
    float acc00 = 0.f, acc01 = 0.f, acc10 = 0.f, acc11 = 0.f;
    for (int k0 = 0; k0 < C; k0 += 32) {
        #pragma unroll
        for (int u = 0; u < 4; u++) {
            int e = t + u * 256;
            int j = e >> 5, r = e & 31;       // consecutive threads -> consecutive r (coalesced)
            float va = 0.f, vb = 0.f;
            if (k0 + j < C) {
                va = Xb[(long)(k0 + j) * Nn + n0 + r];
                vb = Xb[(long)(k0 + j) * Nn + m0 + r];
            }
            sA[r][j] = va;
            sB[r][j] = vb;
        }
        __syncthreads();
        #pragma unroll
        for (int j = 0; j < 32; j++) {
            float a0 = sA[ty * 2][j],     a1 = sA[ty * 2 + 1][j];
            float b0 = sB[tx * 2][j],     b1 = sB[tx * 2 + 1][j];
            acc00 += a0 * b0; acc01 += a0 * b1;
            acc10 += a1 * b0; acc11 += a1 * b1;
        }
        __syncthreads();
    }
    float accs[2][2] = {{acc00, acc01}, {acc10, acc11}};
    for (int i = 0; i < 2; i++)
        for (int j = 0; j < 2; j++) {
            int n = n0 + ty * 2 + i, m = m0 + tx * 2 + j;
            float d = sq[b * Nn + n] + sq[b * Nn + m] - 2.f * accs[i][j];
            if (m == n) d = 3.0e38f;   // exclude self
            pd[((long)b * Nn + n) * Nn + m] = d;
        }
}

// top-K smallest per row via K iterations of block argmin (set permutation-invariant)
__global__ void k_topk(const float* __restrict__ pd, int* __restrict__ idx) {
    int row = blockIdx.x;                       // b*N + n
    __shared__ float sv[Nn];
    __shared__ float rv[128];
    __shared__ int   ri[128];
    int t = threadIdx.x;                        // 128 threads
    const float* p = pd + (long)row * Nn;
    for (int i = t; i < Nn; i += 128) sv[i] = p[i];
    __syncthreads();
    for (int s = 0; s < Kk; s++) {
        float best = 3.9e38f; int bi = 0;
        for (int i = t; i < Nn; i += 128) {
            float v = sv[i];
            if (v < best) { best = v; bi = i; }   // ascending i -> lowest index on tie
        }
        rv[t] = best; ri[t] = bi;
        __syncthreads();
        for (int off = 64; off > 0; off >>= 1) {
            if (t < off) {
                float o = rv[t + off]; int oi = ri[t + off];
                if (o < rv[t] || (o == rv[t] && oi < ri[t])) { rv[t] = o; ri[t] = oi; }
            }
            __syncthreads();
        }
        if (t == 0) { idx[(long)row * Kk + s] = ri[0]; sv[ri[0]] = 3.9e38f; }
        __syncthreads();
    }
}

// self-attention core: one block (128 thr) per point
__global__ void k_attn(const float* __restrict__ X, long bsx, int C,
                       const float* __restrict__ wq, const float* __restrict__ wk,
                       const float* __restrict__ wv, const int* __restrict__ idx,
                       float* __restrict__ out /* [B][C][N] */) {
    int pt = blockIdx.x;
    int b = pt / Nn, n = pt % Nn;
    __shared__ float s_f[128];
    __shared__ float s_nb[Kk * 128];
    __shared__ float s_q[128];
    __shared__ float s_sc[Kk];
    __shared__ float s_w[Kk];
    const float* Xb = X + (long)b * bsx;
    int t = threadIdx.x;

    for (int c = t; c < C; c += 128) s_f[c] = Xb[(long)c * Nn + n];
    const int* ip = idx + (long)pt * Kk;
    for (int e = t; e < Kk * C; e += 128) {
        int j = e / C, c = e - j * C;
        s_nb[j * C + c] = Xb[(long)c * Nn + ip[j]];
    }
    if (t < Kk) s_sc[t] = 0.f;
    __syncthreads();

    // q = feat @ wq.T
    for (int e = t; e < C; e += 128) {
        const float* w = wq + (long)e * C;
        float a = 0.f;
        for (int c = 0; c < C; c++) a += w[c] * s_f[c];
        s_q[e] = a;
    }
    __syncthreads();

    // scores[j] = sum_e q[e] * (nb_j @ wk.T)[e]
    for (int e0 = t; e0 < Kk * C; e0 += 128) {
        int j = e0 / C, e = e0 - j * C;
        const float* w = wk + (long)e * C;
        const float* nb = s_nb + j * C;
        float a = 0.f;
        for (int c = 0; c < C; c++) a += w[c] * nb[c];
        atomicAdd(&s_sc[j], s_q[e] * a);
    }
    __syncthreads();

    if (t == 0) {
        float scale = 1.f / sqrtf((float)C);
        float mx = -3e38f;
        for (int j = 0; j < Kk; j++) { s_sc[j] *= scale; mx = fmaxf(mx, s_sc[j]); }
        float sm = 0.f;
        for (int j = 0; j < Kk; j++) { float e = expf(s_sc[j] - mx); s_w[j] = e; sm += e; }
        float inv = 1.f / sm;
        for (int j = 0; j < Kk; j++) s_w[j] *= inv;
    }
    __syncthreads();

    // out[e] = sum_j w_j * ((nb_j - feat) @ wv.T)[e]
    for (int e = t; e < C; e += 128) {
        const float* w = wv + (long)e * C;
        float acc = 0.f;
        for (int j = 0; j < Kk; j++) {
            const float* nb = s_nb + j * C;
            float dv = 0.f;
            for (int c = 0; c < C; c++) dv += w[c] * (nb[c] - s_f[c]);
            acc += s_w[j] * dv;
        }
        out[((long)b * C + e) * Nn + n] = acc;
    }
}

// 1x1 conv as GEMM: Y[b][o][n] = sum_c W[o][c] * X[b][c][n]
// 64x64 tile, 16x16 threads, 4x4 register blocking
__global__ void k_conv(const float* __restrict__ X, long bsx, int C,
                       const float* __restrict__ W, int O,
                       float* __restrict__ Y, long bsy) {
    int b  = blockIdx.z;
    int n0 = blockIdx.x * 64;
    int o0 = blockIdx.y * 64;
    __shared__ float sW[16][65];
    __shared__ float sX[16][65];
    int tx = threadIdx.x, ty = threadIdx.y;
    int t = ty * 16 + tx;
    float acc[4][4];
    #pragma unroll
    for (int i = 0; i < 4; i++)
        #pragma unroll
        for (int j = 0; j < 4; j++) acc[i][j] = 0.f;
    const float* Xb = X + (long)b * bsx;
    for (int kk = 0; kk < C; kk += 16) {
        #pragma unroll
        for (int u = 0; u < 4; u++) {
            int e = t + u * 256;
            int c = e & 15, o = e >> 4;
            sW[c][o] = (o0 + o < O && kk + c < C) ? W[(long)(o0 + o) * C + kk + c] : 0.f;
        }
        #pragma unroll
        for (int u = 0; u < 4; u++) {
            int e = t + u * 256;
            int c = e >> 6, n = e & 63;
            sX[c][n] = (kk + c < C) ? Xb[(long)(kk + c) * Nn + n0 + n] : 0.f;
        }
        __syncthreads();
        #pragma unroll
        for (int c = 0; c < 16; c++) {
            float a[4], bv[4];
            #pragma unroll
            for (int i = 0; i < 4; i++) a[i] = sW[c][ty + 16 * i];
            #pragma unroll
            for (int j = 0; j < 4; j++) bv[j] = sX[c][tx + 16 * j];
            #pragma unroll
            for (int i = 0; i < 4; i++)
                #pragma unroll
                for (int j = 0; j < 4; j++) acc[i][j] += a[i] * bv[j];
        }
        __syncthreads();
    }
    for (int i = 0; i < 4; i++) {
        int o = o0 + ty + 16 * i;
        if (o >= O) continue;
        float* yp = Y + (long)b * bsy + (long)o * Nn + n0;
        #pragma unroll
        for (int j = 0; j < 4; j++) yp[tx + 16 * j] = acc[i][j];
    }
}

// per-channel batch stats over (B,N)
__global__ void k_bnstats(const float* __restrict__ Y, long bsy,
                          float* __restrict__ mean, float* __restrict__ rstd) {
    int o = blockIdx.x;
    int t = threadIdx.x;
    float s1 = 0.f, s2 = 0.f;
    for (int i = t; i < Bb * Nn; i += 256) {
        int b = i / Nn, n = i % Nn;
        float v = Y[(long)b * bsy + (long)o * Nn + n];
        s1 += v; s2 += v * v;
    }
    __shared__ float r1[256], r2[256];
    r1[t] = s1; r2[t] = s2;
    __syncthreads();
    for (int off = 128; off > 0; off >>= 1) {
        if (t < off) { r1[t] += r1[t + off]; r2[t] += r2[t + off]; }
        __syncthreads();
    }
    if (t == 0) {
        float m = r1[0] / (float)(Bb * Nn);
        float v = r2[0] / (float)(Bb * Nn) - m * m;
        mean[o] = m;
        rstd[o] = rsqrtf(v + 1e-5f);
    }
}

// in-place normalize + LeakyReLU(0.2)
__global__ void k_bnapply(float* __restrict__ Y, long bsy, int O,
                          const float* __restrict__ mean, const float* __restrict__ rstd) {
    long total = (long)Bb * O * Nn;
    for (long i = (long)blockIdx.x * blockDim.x + threadIdx.x; i < total;
         i += (long)gridDim.x * blockDim.x) {
        int n = (int)(i % Nn);
        long bo = i / Nn;
        int o = (int)(bo % O);
        int b = (int)(bo / O);
        float* p = Y + (long)b * bsy + (long)o * Nn + n;
        float v = (*p - mean[o]) * rstd[o];
        *p = v >= 0.f ? v : 0.2f * v;
    }
}

// strided copy (concat of raw x into h)
__global__ void k_copy(const float* __restrict__ X, long bsx,
                       float* __restrict__ D, long bsd, int C) {
    long total = (long)Bb * C * Nn;
    for (long i = (long)blockIdx.x * blockDim.x + threadIdx.x; i < total;
         i += (long)gridDim.x * blockDim.x) {
        int n = (int)(i % Nn);
        long bc = i / Nn;
        int c = (int)(bc % C);
        int b = (int)(bc / C);
        D[(long)b * bsd + (long)c * Nn + n] = X[(long)b * bsx + (long)c * Nn + n];
    }
}

// global max+mean pool over N: p[b][c]=max, p[b][1024+c]=mean
__global__ void k_pool(const float* __restrict__ X5, float* __restrict__ p) {
    int bc = blockIdx.x;
    int b = bc / 1024, c = bc % 1024;
    const float* xp = X5 + ((long)b * 1024 + c) * Nn;
    int t = threadIdx.x;
    float mx = -3e38f, sm = 0.f;
    for (int n = t; n < Nn; n += 256) { float v = xp[n]; mx = fmaxf(mx, v); sm += v; }
    __shared__ float smx[256], ssm[256];
    smx[t] = mx; ssm[t] = sm;
    __syncthreads();
    for (int off = 128; off > 0; off >>= 1) {
        if (t < off) { smx[t] = fmaxf(smx[t], smx[t + off]); ssm[t] += ssm[t + off]; }
        __syncthreads();
    }
    if (t == 0) {
        p[b * 2048 + c]        = smx[0];
        p[b * 2048 + 1024 + c] = ssm[0] / (float)Nn;
    }
}

// dense layer: one warp per output scalar
__global__ void k_linear(const float* __restrict__ in, const float* __restrict__ W,
                         const float* __restrict__ bias, float* __restrict__ out,
                         int I, int O) {
    int w = (blockIdx.x * blockDim.x + threadIdx.x) >> 5;
    int lane = threadIdx.x & 31;
    if (w >= Bb * O) return;
    int b = w / O, o = w % O;
    const float* ip = in + (long)b * I;
    const float* wp = W + (long)o * I;
    float a = 0.f;
    for (int i = lane; i < I; i += 32) a += ip[i] * wp[i];
    for (int off = 16; off > 0; off >>= 1) a += __shfl_down_sync(0xffffffffu, a, off);
    if (lane == 0) out[w] = a + bias[o];
}

// BatchNorm over batch (B=8) + LeakyReLU, in place
__global__ void k_bnf(float* __restrict__ Y, int O) {
    int o = blockIdx.x * blockDim.x + threadIdx.x;
    if (o >= O) return;
    float s1 = 0.f, s2 = 0.f;
    for (int b = 0; b < Bb; b++) { float v = Y[b * O + o]; s1 += v; s2 += v * v; }
    float m = s1 / (float)Bb;
    float v = s2 / (float)Bb - m * m;
    float r = rsqrtf(v + 1e-5f);
    for (int b = 0; b < Bb; b++) {
        float u = (Y[b * O + o] - m) * r;
        Y[b * O + o] = u >= 0.f ? u : 0.2f * u;
    }
}

// ---------------- host orchestration ----------------------------------------

static void conv_bn_h(const float* X, long bsx, int C, const float* W, int O,
                      float* Y, long bsy, float* mean, float* rstd) {
    dim3 gg(Nn / 64, (O + 63) / 64, Bb);
    k_conv<<<gg, dim3(16, 16)>>>(X, bsx, C, W, O, Y, bsy);
    k_bnstats<<<O, 256>>>(Y, bsy, mean, rstd);
    long total = (long)Bb * O * Nn;
    k_bnapply<<<(int)((total + 255) / 256), 256>>>(Y, bsy, O, mean, rstd);
}

static void self_att_h(const float* X, long bsx, int C,
                       const float* wq, const float* wk, const float* wv, const float* wc,
                       float* H, long bsh,
                       float* pd, int* idx, float* sq, float* att,
                       float* mean, float* rstd) {
    k_sqnorm<<<(Bb * Nn + 255) / 256, 256>>>(X, bsx, C, sq);
    k_dist<<<dim3(Nn / 32, Nn / 32, Bb), dim3(16, 16)>>>(X, bsx, C, sq, pd);
    k_topk<<<Bb * Nn, 128>>>(pd, idx);
    k_attn<<<Bb * Nn, 128>>>(X, bsx, C, wq, wk, wv, idx, att);
    conv_bn_h(att, (long)C * Nn, C, wc, C, H, bsh, mean, rstd);   // res -> channels [0,C)
    long total = (long)Bb * C * Nn;
    k_copy<<<(int)((total + 255) / 256), 256>>>(X, bsx, H + (long)C * Nn, bsh, C);
}

extern "C" void kernel_launch(void* const* d_in, const int* in_sizes, int n_in,
                              void* d_out, int out_size) {
    const float* x = (const float*)d_in[0];
    const float* sa_wq[4] = {(const float*)d_in[1],  (const float*)d_in[5],
                             (const float*)d_in[9],  (const float*)d_in[13]};
    const float* sa_wk[4] = {(const float*)d_in[2],  (const float*)d_in[6],
                             (const float*)d_in[10], (const float*)d_in[14]};
    const float* sa_wv[4] = {(const float*)d_in[3],  (const float*)d_in[7],
                             (const float*)d_in[11], (const float*)d_in[15]};
    const float* sa_wc[4] = {(const float*)d_in[4],  (const float*)d_in[8],
                             (const float*)d_in[12], (const float*)d_in[16]};
    const float* conv1_w = (const float*)d_in[17];
    const float* conv2_w = (const float*)d_in[18];
    const float* conv3_w = (const float*)d_in[19];
    const float* conv4_w = (const float*)d_in[20];
    const float* conv5_w = (const float*)d_in[21];
    const float* lin1_w = (const float*)d_in[22];
    const float* lin1_b = (const float*)d_in[23];
    const float* lin2_w = (const float*)d_in[24];
    const float* lin2_b = (const float*)d_in[25];
    const float* lin3_w = (const float*)d_in[26];
    const float* lin3_b = (const float*)d_in[27];

    float *pd, *sq, *att, *h, *xc, *x5, *mean, *rstd, *p, *f1, *f2;
    int* idx;
    cudaGetSymbolAddress((void**)&pd,   g_pd);
    cudaGetSymbolAddress((void**)&idx,  g_idx);
    cudaGetSymbolAddress((void**)&sq,   g_sq);
    cudaGetSymbolAddress((void**)&h,    g_h);
    cudaGetSymbolAddress((void**)&att,  g_att);
    cudaGetSymbolAddress((void**)&xc,   g_xc);
    cudaGetSymbolAddress((void**)&x5,   g_x5);
    cudaGetSymbolAddress((void**)&mean, g_mean);
    cudaGetSymbolAddress((void**)&rstd, g_rstd);
    cudaGetSymbolAddress((void**)&p,    g_p);
    cudaGetSymbolAddress((void**)&f1,   g_f1);
    cudaGetSymbolAddress((void**)&f2,   g_f2);

    const long bxc = (long)512 * Nn;   // batch stride of xc

    // SA1: x [8,3,N] -> h [8,6,N]
    self_att_h(x, (long)3 * Nn, 3, sa_wq[0], sa_wk[0], sa_wv[0], sa_wc[0],
               h, (long)6 * Nn, pd, idx, sq, att, mean, rstd);
    // conv1: h[6] -> x1[64] (xc channels 0..63)
    conv_bn_h(h, (long)6 * Nn, 6, conv1_w, 64, xc, bxc, mean, rstd);

    // SA2: x1 -> h [8,128,N]
    self_att_h(xc, bxc, 64, sa_wq[1], sa_wk[1], sa_wv[1], sa_wc[1],
               h, (long)128 * Nn, pd, idx, sq, att, mean, rstd);
    // conv2: h[128] -> x2[64] (xc channels 64..127)
    conv_bn_h(h, (long)128 * Nn, 128, conv2_w, 64, xc + (long)64 * Nn, bxc, mean, rstd);

    // SA3: x2 -> h [8,128,N]
    self_att_h(xc + (long)64 * Nn, bxc, 64, sa_wq[2], sa_wk[2], sa_wv[2], sa_wc[2],
               h, (long)128 * Nn, pd, idx, sq, att, mean, rstd);
    // conv3: h[128] -> x3[128] (xc channels 128..255)
    conv_bn_h(h, (long)128 * Nn, 128, conv3_w, 128, xc + (long)128 * Nn, bxc, mean, rstd);

    // SA4: x3 -> h [8,256,N]
    self_att_h(xc + (long)128 * Nn, bxc, 128, sa_wq[3], sa_wk[3], sa_wv[3], sa_wc[3],
               h, (long)256 * Nn, pd, idx, sq, att, mean, rstd);
    // conv4: h[256] -> x4[256] (xc channels 256..511)
    conv_bn_h(h, (long)256 * Nn, 256, conv4_w, 256, xc + (long)256 * Nn, bxc, mean, rstd);

    // conv5: xc[512] -> x5[1024]
    conv_bn_h(xc, bxc, 512, conv5_w, 1024, x5, (long)1024 * Nn, mean, rstd);

    // pooling -> p [8,2048]
    k_pool<<<Bb * 1024, 256>>>(x5, p);

    // MLP head
    k_linear<<<(Bb * 512 + 7) / 8, 256>>>(p, lin1_w, lin1_b, f1, 2048, 512);
    k_bnf<<<2, 256>>>(f1, 512);
    k_linear<<<(Bb * 256 + 7) / 8, 256>>>(f1, lin2_w, lin2_b, f2, 512, 256);
    k_bnf<<<1, 256>>>(f2, 256);
    k_linear<<<(Bb * 40 + 7) / 8, 256>>>(f2, lin3_w, lin3_b, (float*)d_out, 256, 40);
}

// round 4
// speedup vs baseline: 18.4247x; 18.4247x over previous
#include <cuda_runtime.h>
#include <math.h>

#define Bb 8
#define Nn 2048
#define Kk 20

// ---------------- scratch (static device globals; no allocation) -------------
__device__ float g_pd[(size_t)Bb * Nn * Nn];     // 134 MB distance matrix
__device__ int   g_idx[Bb * Nn * Kk];            // knn indices
__device__ float g_sq[Bb * Nn];                  // squared norms
__device__ float g_h[(size_t)Bb * 256 * Nn];     // concat buffer (max 256 ch)
__device__ float g_att[(size_t)Bb * 128 * Nn];   // attention weighted-diff M
__device__ float g_qk[(size_t)Bb * 128 * Nn];    // Wqk @ X
__device__ float g_xt[(size_t)Bb * Nn * 128];    // X transposed [B,N,C]
__device__ float g_qkt[(size_t)Bb * Nn * 128];   // QK transposed [B,N,C]
__device__ float g_wqk[128 * 128];               // wk^T wq
__device__ float g_wcv[128 * 128];               // wc wv
__device__ float g_xc[(size_t)Bb * 512 * Nn];    // x1|x2|x3|x4 concat
__device__ float g_x5[(size_t)Bb * 1024 * Nn];   // conv5 output
__device__ float g_mean[1024];
__device__ float g_rstd[1024];
__device__ float g_p[Bb * 2048];
__device__ float g_f1[Bb * 512];
__device__ float g_f2[Bb * 256];

// ---------------- kernels ----------------------------------------------------

__global__ void k_sqnorm(const float* __restrict__ X, long bsx, int C,
                         float* __restrict__ sq) {
    int i = blockIdx.x * blockDim.x + threadIdx.x;
    if (i >= Bb * Nn) return;
    int b = i / Nn, n = i % Nn;
    const float* xp = X + (long)b * bsx + n;
    float s = 0.f;
    for (int c = 0; c < C; c++) { float v = xp[(long)c * Nn]; s += v * v; }
    sq[i] = s;
}

// squared distance matrix: pd[b][n][m] ; diag=INF
__global__ void k_dist(const float* __restrict__ X, long bsx, int C,
                       const float* __restrict__ sq, float* __restrict__ pd) {
    int b = blockIdx.z;
    int n0 = blockIdx.y * 32, m0 = blockIdx.x * 32;
    __shared__ float sA[32][33], sB[32][33];
    const float* Xb = X + (long)b * bsx;
    int tx = threadIdx.x, ty = threadIdx.y;   // 16x16
    int t = ty * 16 + tx;
    float acc00 = 0.f, acc01 = 0.f, acc10 = 0.f, acc11 = 0.f;
    for (int k0 = 0; k0 < C; k0 += 32) {
        #pragma unroll
        for (int u = 0; u < 4; u++) {
            int e = t + u * 256;
            int j = e >> 5, r = e & 31;
            float va = 0.f, vb = 0.f;
            if (k0 + j < C) {
                va = Xb[(long)(k0 + j) * Nn + n0 + r];
                vb = Xb[(long)(k0 + j) * Nn + m0 + r];
            }
            sA[r][j] = va;
            sB[r][j] = vb;
        }
        __syncthreads();
        #pragma unroll
        for (int j = 0; j < 32; j++) {
            float a0 = sA[ty * 2][j],     a1 = sA[ty * 2 + 1][j];
            float b0 = sB[tx * 2][j],     b1 = sB[tx * 2 + 1][j];
            acc00 += a0 * b0; acc01 += a0 * b1;
            acc10 += a1 * b0; acc11 += a1 * b1;
        }
        __syncthreads();
    }
    float accs[2][2] = {{acc00, acc01}, {acc10, acc11}};
    for (int i = 0; i < 2; i++)
        for (int j = 0; j < 2; j++) {
            int n = n0 + ty * 2 + i, m = m0 + tx * 2 + j;
            float d = sq[b * Nn + n] + sq[b * Nn + m] - 2.f * accs[i][j];
            if (m == n) d = 3.0e38f;
            pd[((long)b * Nn + n) * Nn + m] = d;
        }
}

// top-K smallest per row via K iterations of block argmin
__global__ void k_topk(const float* __restrict__ pd, int* __restrict__ idx) {
    int row = blockIdx.x;                       // b*N + n
    __shared__ float sv[Nn];
    __shared__ float rv[128];
    __shared__ int   ri[128];
    int t = threadIdx.x;                        // 128 threads
    const float* p = pd + (long)row * Nn;
    for (int i = t; i < Nn; i += 128) sv[i] = p[i];
    __syncthreads();
    for (int s = 0; s < Kk; s++) {
        float best = 3.9e38f; int bi = 0;
        for (int i = t; i < Nn; i += 128) {
            float v = sv[i];
            if (v < best) { best = v; bi = i; }
        }
        rv[t] = best; ri[t] = bi;
        __syncthreads();
        for (int off = 64; off > 0; off >>= 1) {
            if (t < off) {
                float o = rv[t + off]; int oi = ri[t + off];
                if (o < rv[t] || (o == rv[t] && oi < ri[t])) { rv[t] = o; ri[t] = oi; }
            }
            __syncthreads();
        }
        if (t == 0) { idx[(long)row * Kk + s] = ri[0]; sv[ri[0]] = 3.9e38f; }
        __syncthreads();
    }
}

// transpose [B,C,N] -> [B,N,C] (zero-fill beyond C not needed; guarded)
__global__ void k_transpose(const float* __restrict__ X, long bsx, int C,
                            float* __restrict__ XT) {
    __shared__ float tile[32][33];
    int b = blockIdx.z;
    int n0 = blockIdx.x * 32, c0 = blockIdx.y * 32;
    for (int i = threadIdx.y; i < 32; i += 8) {
        int c = c0 + i;
        tile[i][threadIdx.x] = (c < C) ? X[(long)b * bsx + (long)c * Nn + n0 + threadIdx.x] : 0.f;
    }
    __syncthreads();
    for (int i = threadIdx.y; i < 32; i += 8) {
        int n = n0 + i, c = c0 + threadIdx.x;
        if (c < C) XT[((long)b * Nn + n) * C + c] = tile[threadIdx.x][i];
    }
}

// Wqk[i][j] = sum_e wk[e][i] * wq[e][j]   (= (wk^T wq)[i][j])
__global__ void k_wqk(const float* __restrict__ wk, const float* __restrict__ wq,
                      float* __restrict__ out, int C) {
    int j = blockIdx.x * 16 + threadIdx.x;
    int i = blockIdx.y * 16 + threadIdx.y;
    if (i >= C || j >= C) return;
    float a = 0.f;
    for (int e = 0; e < C; e++) a += wk[e * C + i] * wq[e * C + j];
    out[i * C + j] = a;
}

// Wcv[i][j] = sum_v wc[i][v] * wv[v][j]
__global__ void k_wcv(const float* __restrict__ wc, const float* __restrict__ wv,
                      float* __restrict__ out, int C) {
    int j = blockIdx.x * 16 + threadIdx.x;
    int i = blockIdx.y * 16 + threadIdx.y;
    if (i >= C || j >= C) return;
    float a = 0.f;
    for (int v = 0; v < C; v++) a += wc[i * C + v] * wv[v * C + j];
    out[i * C + j] = a;
}

// attention gather/softmax: one warp per point, 32 points per block (1024 thr)
// scores_j = qk_n . x_{i_j};  M[.,c,n] = sum_j softmax_j * x_{i_j}[c] - x_n[c]
__global__ void k_attn2(const float* __restrict__ XT, const float* __restrict__ QKT,
                        int C, const int* __restrict__ idx,
                        float* __restrict__ M, long bsm) {
    __shared__ float s_m[128][33];
    const unsigned FULL = 0xffffffffu;
    int w = threadIdx.x >> 5, lane = threadIdx.x & 31;
    int pt = blockIdx.x * 32 + w;
    int b = pt / Nn;
    int n0 = (blockIdx.x & 63) * 32;           // 64 blocks per batch (2048/32)
    int NR = (C + 31) >> 5;

    float qk[4], f[4];
    const float* qrow = QKT + (long)pt * C;
    const float* frow = XT + (long)pt * C;
    #pragma unroll
    for (int r = 0; r < 4; r++) {
        int c = lane + 32 * r;
        bool ok = (r < NR) && (c < C);
        qk[r] = ok ? qrow[c] : 0.f;
        f[r]  = ok ? frow[c] : 0.f;
    }
    const int* ip = idx + (long)pt * Kk;

    // pass 1: scores
    float myscore = 0.f;
    for (int j = 0; j < Kk; j++) {
        int ij = ip[j];
        const float* nrow = XT + ((long)b * Nn + ij) * C;
        float p = 0.f;
        #pragma unroll
        for (int r = 0; r < 4; r++) {
            int c = lane + 32 * r;
            if (r < NR && c < C) p += qk[r] * nrow[c];
        }
        #pragma unroll
        for (int off = 16; off > 0; off >>= 1) p += __shfl_xor_sync(FULL, p, off);
        if (lane == j) myscore = p;            // j < 20 < 32
    }
    // softmax over lanes 0..19
    float scale = rsqrtf((float)C);
    float val = (lane < Kk) ? myscore * scale : -3.0e38f;
    float mx = val;
    #pragma unroll
    for (int off = 16; off > 0; off >>= 1) mx = fmaxf(mx, __shfl_xor_sync(FULL, mx, off));
    float e = (lane < Kk) ? expf(val - mx) : 0.f;
    float sm = e;
    #pragma unroll
    for (int off = 16; off > 0; off >>= 1) sm += __shfl_xor_sync(FULL, sm, off);
    float wme = e / sm;

    // pass 2: weighted sum of neighbors
    float m[4] = {0.f, 0.f, 0.f, 0.f};
    for (int j = 0; j < Kk; j++) {
        float wj = __shfl_sync(FULL, wme, j);
        int ij = ip[j];
        const float* nrow = XT + ((long)b * Nn + ij) * C;
        #pragma unroll
        for (int r = 0; r < 4; r++) {
            int c = lane + 32 * r;
            if (r < NR && c < C) m[r] += wj * nrow[c];
        }
    }
    #pragma unroll
    for (int r = 0; r < 4; r++) m[r] -= f[r];

    // stage + coalesced write to [B,C,N]
    #pragma unroll
    for (int r = 0; r < 4; r++) {
        int c = lane + 32 * r;
        if (r < NR && c < C) s_m[c][w] = m[r];
    }
    __syncthreads();
    int t = threadIdx.x;
    for (int e2 = t; e2 < C * 32; e2 += 1024) {
        int c = e2 >> 5, p2 = e2 & 31;
        M[(long)b * bsm + (long)c * Nn + n0 + p2] = s_m[c][p2];
    }
}

// 1x1 conv as GEMM: Y[b][o][n] = sum_c W[o][c] * X[b][c][n]
__global__ void k_conv(const float* __restrict__ X, long bsx, int C,
                       const float* __restrict__ W, int O,
                       float* __restrict__ Y, long bsy) {
    int b  = blockIdx.z;
    int n0 = blockIdx.x * 64;
    int o0 = blockIdx.y * 64;
    __shared__ float sW[16][65];
    __shared__ float sX[16][65];
    int tx = threadIdx.x, ty = threadIdx.y;
    int t = ty * 16 + tx;
    float acc[4][4];
    #pragma unroll
    for (int i = 0; i < 4; i++)
        #pragma unroll
        for (int j = 0; j < 4; j++) acc[i][j] = 0.f;
    const float* Xb = X + (long)b * bsx;
    for (int kk = 0; kk < C; kk += 16) {
        #pragma unroll
        for (int u = 0; u < 4; u++) {
            int e = t + u * 256;
            int c = e & 15, o = e >> 4;
            sW[c][o] = (o0 + o < O && kk + c < C) ? W[(long)(o0 + o) * C + kk + c] : 0.f;
        }
        #pragma unroll
        for (int u = 0; u < 4; u++) {
            int e = t + u * 256;
            int c = e >> 6, n = e & 63;
            sX[c][n] = (kk + c < C) ? Xb[(long)(kk + c) * Nn + n0 + n] : 0.f;
        }
        __syncthreads();
        #pragma unroll
        for (int c = 0; c < 16; c++) {
            float a[4], bv[4];
            #pragma unroll
            for (int i = 0; i < 4; i++) a[i] = sW[c][ty + 16 * i];
            #pragma unroll
            for (int j = 0; j < 4; j++) bv[j] = sX[c][tx + 16 * j];
            #pragma unroll
            for (int i = 0; i < 4; i++)
                #pragma unroll
                for (int j = 0; j < 4; j++) acc[i][j] += a[i] * bv[j];
        }
        __syncthreads();
    }
    for (int i = 0; i < 4; i++) {
        int o = o0 + ty + 16 * i;
        if (o >= O) continue;
        float* yp = Y + (long)b * bsy + (long)o * Nn + n0;
        #pragma unroll
        for (int j = 0; j < 4; j++) yp[tx + 16 * j] = acc[i][j];
    }
}

// per-channel batch stats over (B,N)
__global__ void k_bnstats(const float* __restrict__ Y, long bsy,
                          float* __restrict__ mean, float* __restrict__ rstd) {
    int o = blockIdx.x;
    int t = threadIdx.x;
    float s1 = 0.f, s2 = 0.f;
    for (int i = t; i < Bb * Nn; i += 256) {
        int b = i / Nn, n = i % Nn;
        float v = Y[(long)b * bsy + (long)o * Nn + n];
        s1 += v; s2 += v * v;
    }
    __shared__ float r1[256], r2[256];
    r1[t] = s1; r2[t] = s2;
    __syncthreads();
    for (int off = 128; off > 0; off >>= 1) {
        if (t < off) { r1[t] += r1[t + off]; r2[t] += r2[t + off]; }
        __syncthreads();
    }
    if (t == 0) {
        float m = r1[0] / (float)(Bb * Nn);
        float v = r2[0] / (float)(Bb * Nn) - m * m;
        mean[o] = m;
        rstd[o] = rsqrtf(v + 1e-5f);
    }
}

// in-place normalize + LeakyReLU(0.2)
__global__ void k_bnapply(float* __restrict__ Y, long bsy, int O,
                          const float* __restrict__ mean, const float* __restrict__ rstd) {
    long total = (long)Bb * O * Nn;
    for (long i = (long)blockIdx.x * blockDim.x + threadIdx.x; i < total;
         i += (long)gridDim.x * blockDim.x) {
        int n = (int)(i % Nn);
        long bo = i / Nn;
        int o = (int)(bo % O);
        int b = (int)(bo / O);
        float* p = Y + (long)b * bsy + (long)o * Nn + n;
        float v = (*p - mean[o]) * rstd[o];
        *p = v >= 0.f ? v : 0.2f * v;
    }
}

// strided copy (concat of raw x into h)
__global__ void k_copy(const float* __restrict__ X, long bsx,
                       float* __restrict__ D, long bsd, int C) {
    long total = (long)Bb * C * Nn;
    for (long i = (long)blockIdx.x * blockDim.x + threadIdx.x; i < total;
         i += (long)gridDim.x * blockDim.x) {
        int n = (int)(i % Nn);
        long bc = i / Nn;
        int c = (int)(bc % C);
        int b = (int)(bc / C);
        D[(long)b * bsd + (long)c * Nn + n] = X[(long)b * bsx + (long)c * Nn + n];
    }
}

// global max+mean pool over N
__global__ void k_pool(const float* __restrict__ X5, float* __restrict__ p) {
    int bc = blockIdx.x;
    int b = bc / 1024, c = bc % 1024;
    const float* xp = X5 + ((long)b * 1024 + c) * Nn;
    int t = threadIdx.x;
    float mx = -3e38f, sm = 0.f;
    for (int n = t; n < Nn; n += 256) { float v = xp[n]; mx = fmaxf(mx, v); sm += v; }
    __shared__ float smx[256], ssm[256];
    smx[t] = mx; ssm[t] = sm;
    __syncthreads();
    for (int off = 128; off > 0; off >>= 1) {
        if (t < off) { smx[t] = fmaxf(smx[t], smx[t + off]); ssm[t] += ssm[t + off]; }
        __syncthreads();
    }
    if (t == 0) {
        p[b * 2048 + c]        = smx[0];
        p[b * 2048 + 1024 + c] = ssm[0] / (float)Nn;
    }
}

// dense layer: one warp per output scalar
__global__ void k_linear(const float* __restrict__ in, const float* __restrict__ W,
                         const float* __restrict__ bias, float* __restrict__ out,
                         int I, int O) {
    int w = (blockIdx.x * blockDim.x + threadIdx.x) >> 5;
    int lane = threadIdx.x & 31;
    if (w >= Bb * O) return;
    int b = w / O, o = w % O;
    const float* ip = in + (long)b * I;
    const float* wp = W + (long)o * I;
    float a = 0.f;
    for (int i = lane; i < I; i += 32) a += ip[i] * wp[i];
    for (int off = 16; off > 0; off >>= 1) a += __shfl_down_sync(0xffffffffu, a, off);
    if (lane == 0) out[w] = a + bias[o];
}

// BatchNorm over batch (B=8) + LeakyReLU, in place
__global__ void k_bnf(float* __restrict__ Y, int O) {
    int o = blockIdx.x * blockDim.x + threadIdx.x;
    if (o >= O) return;
    float s1 = 0.f, s2 = 0.f;
    for (int b = 0; b < Bb; b++) { float v = Y[b * O + o]; s1 += v; s2 += v * v; }
    float m = s1 / (float)Bb;
    float v = s2 / (float)Bb - m * m;
    float r = rsqrtf(v + 1e-5f);
    for (int b = 0; b < Bb; b++) {
        float u = (Y[b * O + o] - m) * r;
        Y[b * O + o] = u >= 0.f ? u : 0.2f * u;
    }
}

// ---------------- host orchestration ----------------------------------------

static void conv_bn_h(const float* X, long bsx, int C, const float* W, int O,
                      float* Y, long bsy, float* mean, float* rstd) {
    dim3 gg(Nn / 64, (O + 63) / 64, Bb);
    k_conv<<<gg, dim3(16, 16)>>>(X, bsx, C, W, O, Y, bsy);
    k_bnstats<<<O, 256>>>(Y, bsy, mean, rstd);
    long total = (long)Bb * O * Nn;
    k_bnapply<<<(int)((total + 255) / 256), 256>>>(Y, bsy, O, mean, rstd);
}

struct Scratch {
    float *pd, *sq, *att, *qk, *xt, *qkt, *wqk, *wcv, *h, *xc, *x5, *mean, *rstd, *p, *f1, *f2;
    int* idx;
};

static void self_att_h(const float* X, long bsx, int C,
                       const float* wq, const float* wk, const float* wv, const float* wc,
                       float* H, long bsh, const Scratch& S) {
    k_sqnorm<<<(Bb * Nn + 255) / 256, 256>>>(X, bsx, C, S.sq);
    k_dist<<<dim3(Nn / 32, Nn / 32, Bb), dim3(16, 16)>>>(X, bsx, C, S.sq, S.pd);
    k_topk<<<Bb * Nn, 128>>>(S.pd, S.idx);

    // transpose X -> XT [B,N,C]
    dim3 tg(Nn / 32, (C + 31) / 32, Bb);
    k_transpose<<<tg, dim3(32, 8)>>>(X, bsx, C, S.xt);

    // Wqk = wk^T wq ; QK = Wqk @ X ; transpose -> QKT
    dim3 sg((C + 15) / 16, (C + 15) / 16);
    k_wqk<<<sg, dim3(16, 16)>>>(wk, wq, S.wqk, C);
    dim3 cg(Nn / 64, (C + 63) / 64, Bb);
    k_conv<<<cg, dim3(16, 16)>>>(X, bsx, C, S.wqk, C, S.qk, (long)C * Nn);
    k_transpose<<<tg, dim3(32, 8)>>>(S.qk, (long)C * Nn, C, S.qkt);

    // gather + softmax + weighted diff -> M (g_att, [B,C,N])
    k_attn2<<<Bb * Nn / 32, 1024>>>(S.xt, S.qkt, C, S.idx, S.att, (long)C * Nn);

    // res = conv_bn(Wcv @ M)  where Wcv = wc @ wv
    k_wcv<<<sg, dim3(16, 16)>>>(wc, wv, S.wcv, C);
    conv_bn_h(S.att, (long)C * Nn, C, S.wcv, C, H, bsh, S.mean, S.rstd);

    // concat raw x into channels [C, 2C)
    long total = (long)Bb * C * Nn;
    k_copy<<<(int)((total + 255) / 256), 256>>>(X, bsx, H + (long)C * Nn, bsh, C);
}

extern "C" void kernel_launch(void* const* d_in, const int* in_sizes, int n_in,
                              void* d_out, int out_size) {
    const float* x = (const float*)d_in[0];
    const float* sa_wq[4] = {(const float*)d_in[1],  (const float*)d_in[5],
                             (const float*)d_in[9],  (const float*)d_in[13]};
    const float* sa_wk[4] = {(const float*)d_in[2],  (const float*)d_in[6],
                             (const float*)d_in[10], (const float*)d_in[14]};
    const float* sa_wv[4] = {(const float*)d_in[3],  (const float*)d_in[7],
                             (const float*)d_in[11], (const float*)d_in[15]};
    const float* sa_wc[4] = {(const float*)d_in[4],  (const float*)d_in[8],
                             (const float*)d_in[12], (const float*)d_in[16]};
    const float* conv1_w = (const float*)d_in[17];
    const float* conv2_w = (const float*)d_in[18];
    const float* conv3_w = (const float*)d_in[19];
    const float* conv4_w = (const float*)d_in[20];
    const float* conv5_w = (const float*)d_in[21];
    const float* lin1_w = (const float*)d_in[22];
    const float* lin1_b = (const float*)d_in[23];
    const float* lin2_w = (const float*)d_in[24];
    const float* lin2_b = (const float*)d_in[25];
    const float* lin3_w = (const float*)d_in[26];
    const float* lin3_b = (const float*)d_in[27];

    Scratch S;
    cudaGetSymbolAddress((void**)&S.pd,   g_pd);
    cudaGetSymbolAddress((void**)&S.idx,  g_idx);
    cudaGetSymbolAddress((void**)&S.sq,   g_sq);
    cudaGetSymbolAddress((void**)&S.h,    g_h);
    cudaGetSymbolAddress((void**)&S.att,  g_att);
    cudaGetSymbolAddress((void**)&S.qk,   g_qk);
    cudaGetSymbolAddress((void**)&S.xt,   g_xt);
    cudaGetSymbolAddress((void**)&S.qkt,  g_qkt);
    cudaGetSymbolAddress((void**)&S.wqk,  g_wqk);
    cudaGetSymbolAddress((void**)&S.wcv,  g_wcv);
    cudaGetSymbolAddress((void**)&S.xc,   g_xc);
    cudaGetSymbolAddress((void**)&S.x5,   g_x5);
    cudaGetSymbolAddress((void**)&S.mean, g_mean);
    cudaGetSymbolAddress((void**)&S.rstd, g_rstd);
    cudaGetSymbolAddress((void**)&S.p,    g_p);
    cudaGetSymbolAddress((void**)&S.f1,   g_f1);
    cudaGetSymbolAddress((void**)&S.f2,   g_f2);

    const long bxc = (long)512 * Nn;   // batch stride of xc

    // SA1: x [8,3,N] -> h [8,6,N]
    self_att_h(x, (long)3 * Nn, 3, sa_wq[0], sa_wk[0], sa_wv[0], sa_wc[0],
               S.h, (long)6 * Nn, S);
    conv_bn_h(S.h, (long)6 * Nn, 6, conv1_w, 64, S.xc, bxc, S.mean, S.rstd);

    // SA2: x1 -> h [8,128,N]
    self_att_h(S.xc, bxc, 64, sa_wq[1], sa_wk[1], sa_wv[1], sa_wc[1],
               S.h, (long)128 * Nn, S);
    conv_bn_h(S.h, (long)128 * Nn, 128, conv2_w, 64, S.xc + (long)64 * Nn, bxc, S.mean, S.rstd);

    // SA3: x2 -> h [8,128,N]
    self_att_h(S.xc + (long)64 * Nn, bxc, 64, sa_wq[2], sa_wk[2], sa_wv[2], sa_wc[2],
               S.h, (long)128 * Nn, S);
    conv_bn_h(S.h, (long)128 * Nn, 128, conv3_w, 128, S.xc + (long)128 * Nn, bxc, S.mean, S.rstd);

    // SA4: x3 -> h [8,256,N]
    self_att_h(S.xc + (long)128 * Nn, bxc, 128, sa_wq[3], sa_wk[3], sa_wv[3], sa_wc[3],
               S.h, (long)256 * Nn, S);
    conv_bn_h(S.h, (long)256 * Nn, 256, conv4_w, 256, S.xc + (long)256 * Nn, bxc, S.mean, S.rstd);

    // conv5: xc[512] -> x5[1024]
    conv_bn_h(S.xc, bxc, 512, conv5_w, 1024, S.x5, (long)1024 * Nn, S.mean, S.rstd);

    // pooling -> p [8,2048]
    k_pool<<<Bb * 1024, 256>>>(S.x5, S.p);

    // MLP head
    k_linear<<<(Bb * 512 + 7) / 8, 256>>>(S.p, lin1_w, lin1_b, S.f1, 2048, 512);
    k_bnf<<<2, 256>>>(S.f1, 512);
    k_linear<<<(Bb * 256 + 7) / 8, 256>>>(S.f1, lin2_w, lin2_b, S.f2, 512, 256);
    k_bnf<<<1, 256>>>(S.f2, 256);
    k_linear<<<(Bb * 40 + 7) / 8, 256>>>(S.f2, lin3_w, lin3_b, (float*)d_out, 256, 40);
}

// round 5
// speedup vs baseline: 19.6386x; 1.0659x over previous
#include <cuda_runtime.h>
#include <math.h>

#define Bb 8
#define Nn 2048
#define Kk 20

// ---------------- scratch (static device globals; no allocation) -------------
__device__ float g_pd[(size_t)Bb * Nn * Nn];     // 134 MB distance matrix
__device__ int   g_idx[Bb * Nn * Kk];            // knn indices
__device__ float g_sq[Bb * Nn];                  // squared norms
__device__ float g_h[(size_t)Bb * 256 * Nn];     // concat buffer (max 256 ch)
__device__ float g_att[(size_t)Bb * 128 * Nn];   // attention weighted-diff M
__device__ float g_qk[(size_t)Bb * 128 * Nn];    // Wqk @ X
__device__ float g_xt[(size_t)Bb * Nn * 128];    // X transposed [B,N,C]
__device__ float g_qkt[(size_t)Bb * Nn * 128];   // QK transposed [B,N,C]
__device__ float g_wqk[128 * 128];               // wk^T wq
__device__ float g_wcv[128 * 128];               // wc wv
__device__ float g_xc[(size_t)Bb * 512 * Nn];    // x1|x2|x3|x4 concat
__device__ float g_x5[(size_t)Bb * 1024 * Nn];   // conv5 output
__device__ float g_mean[1024];
__device__ float g_rstd[1024];
__device__ float g_p[Bb * 2048];
__device__ float g_f1[Bb * 512];
__device__ float g_f2[Bb * 256];

// ---------------- kernels ----------------------------------------------------

__global__ void k_sqnorm(const float* __restrict__ X, long bsx, int C,
                         float* __restrict__ sq) {
    int i = blockIdx.x * blockDim.x + threadIdx.x;
    if (i >= Bb * Nn) return;
    int b = i / Nn, n = i % Nn;
    const float* xp = X + (long)b * bsx + n;
    float s = 0.f;
    for (int c = 0; c < C; c++) { float v = xp[(long)c * Nn]; s += v * v; }
    sq[i] = s;
}

// -------- high-throughput fp32 GEMM --------
// Y[b][o][n] = sum_c A[b?][o][c] * X[b][c][n]
// A row-major [O x C] (lda=C), optional batch stride bsa. BN=128, TN=8, KT=16.
// dist!=0: Y = sq[o] + sq[n] - 2*acc, diag=INF (A is XT, O==Nn).
template<int BM, int TM>
__global__ void k_gemm(const float* __restrict__ A, long bsa, int lda,
                       const float* __restrict__ X, long bsx,
                       int C, int O,
                       float* __restrict__ Y, long bsy,
                       const float* __restrict__ sq, int dist) {
    const int BN = 128, TN = 8, KT = 16;
    __shared__ float sA[KT][BM + 4];
    __shared__ float sX[KT][BN];
    int b  = blockIdx.z;
    int n0 = blockIdx.x * BN;
    int o0 = blockIdx.y * BM;
    int t  = threadIdx.x;          // 256 threads
    int tx = t & 15, ty = t >> 4;
    const float* Ab = A + (long)b * bsa;
    const float* Xb = X + (long)b * bsx;

    float acc[TM][TN];
    #pragma unroll
    for (int i = 0; i < TM; i++)
        #pragma unroll
        for (int j = 0; j < TN; j++) acc[i][j] = 0.f;

    for (int k0 = 0; k0 < C; k0 += KT) {
        #pragma unroll
        for (int u = 0; u < (BM * KT) / 256; u++) {
            int e = t + u * 256;
            int c = e & 15, o = e >> 4;
            float v = 0.f;
            if (k0 + c < C && o0 + o < O) v = Ab[(long)(o0 + o) * lda + k0 + c];
            sA[c][o] = v;
        }
        #pragma unroll
        for (int u = 0; u < (KT * BN) / 256; u++) {
            int e = t + u * 256;
            int n = e & 127, c = e >> 7;
            float v = 0.f;
            if (k0 + c < C) v = Xb[(long)(k0 + c) * Nn + n0 + n];
            sX[c][n] = v;
        }
        __syncthreads();
        #pragma unroll
        for (int kk = 0; kk < KT; kk++) {
            float a[TM], x[TN];
            #pragma unroll
            for (int i = 0; i < TM; i += 4)
                *(float4*)&a[i] = *(const float4*)&sA[kk][ty * TM + i];
            #pragma unroll
            for (int j = 0; j < TN; j += 4)
                *(float4*)&x[j] = *(const float4*)&sX[kk][tx * TN + j];
            #pragma unroll
            for (int i = 0; i < TM; i++)
                #pragma unroll
                for (int j = 0; j < TN; j++) acc[i][j] += a[i] * x[j];
        }
        __syncthreads();
    }

    if (!dist) {
        #pragma unroll
        for (int i = 0; i < TM; i++) {
            int o = o0 + ty * TM + i;
            if (o >= O) continue;
            float* yp = Y + (long)b * bsy + (long)o * Nn + n0 + tx * TN;
            *(float4*)yp       = *(float4*)&acc[i][0];
            *(float4*)(yp + 4) = *(float4*)&acc[i][4];
        }
    } else {
        #pragma unroll
        for (int i = 0; i < TM; i++) {
            int o = o0 + ty * TM + i;
            float sqo = sq[b * Nn + o];
            float4 r[2];
            #pragma unroll
            for (int j = 0; j < TN; j++) {
                int n = n0 + tx * TN + j;
                float d = sqo + sq[b * Nn + n] - 2.f * acc[i][j];
                if (n == o) d = 3.0e38f;
                ((float*)r)[j] = d;
            }
            float* yp = Y + (long)b * bsy + (long)o * Nn + n0 + tx * TN;
            *(float4*)yp       = r[0];
            *(float4*)(yp + 4) = r[1];
        }
    }
}

// top-K smallest per row: warp-segment incremental argmin + merge.
// key = orderable(dist bits) << 11 | col  (min => smallest dist, lowest index)
__global__ void k_topk(const float* __restrict__ pd, int* __restrict__ out) {
    __shared__ unsigned long long sk[Nn];
    __shared__ unsigned long long cand[96];
    int row = blockIdx.x;                  // b*N + n
    int t = threadIdx.x, w = t >> 5, lane = t & 31;
    const unsigned FULL = 0xffffffffu;
    const float* p = pd + (long)row * Nn;
    for (int i = t; i < Nn; i += 128) {
        unsigned bts = __float_as_uint(p[i]);
        bts = (bts & 0x80000000u) ? ~bts : (bts | 0x80000000u);   // order-preserving
        sk[i] = ((unsigned long long)bts << 11) | (unsigned)i;
    }
    __syncthreads();
    int seg = w * 512;
    unsigned long long mymin = ~0ULL;
    #pragma unroll
    for (int j = 0; j < 16; j++) {
        unsigned long long v = sk[seg + lane + 32 * j];
        mymin = v < mymin ? v : mymin;
    }
    for (int s = 0; s < Kk; s++) {
        unsigned long long r = mymin;
        #pragma unroll
        for (int off = 16; off; off >>= 1) {
            unsigned long long o = __shfl_xor_sync(FULL, r, off);
            r = o < r ? o : r;
        }
        if (lane == 0) cand[w * Kk + s] = r;
        if (mymin == r) {                          // unique owner (index in key)
            sk[(int)(r & 2047ULL)] = ~0ULL;
            mymin = ~0ULL;
            #pragma unroll
            for (int j = 0; j < 16; j++) {
                unsigned long long v = sk[seg + lane + 32 * j];
                mymin = v < mymin ? v : mymin;
            }
        }
    }
    __syncthreads();
    if (w == 0) {
        unsigned long long c0 = cand[lane];
        unsigned long long c1 = cand[lane + 32];
        unsigned long long c2 = (lane < 16) ? cand[lane + 64] : ~0ULL;
        for (int s = 0; s < Kk; s++) {
            unsigned long long m = c0 < c1 ? c0 : c1;
            m = c2 < m ? c2 : m;
            unsigned long long r = m;
            #pragma unroll
            for (int off = 16; off; off >>= 1) {
                unsigned long long o = __shfl_xor_sync(FULL, r, off);
                r = o < r ? o : r;
            }
            if (lane == 0) out[(long)row * Kk + s] = (int)(r & 2047ULL);
            if (c0 == r) c0 = ~0ULL;
            else if (c1 == r) c1 = ~0ULL;
            else if (c2 == r) c2 = ~0ULL;
        }
    }
}

// transpose [B,C,N] -> [B,N,C]
__global__ void k_transpose(const float* __restrict__ X, long bsx, int C,
                            float* __restrict__ XT) {
    __shared__ float tile[32][33];
    int b = blockIdx.z;
    int n0 = blockIdx.x * 32, c0 = blockIdx.y * 32;
    for (int i = threadIdx.y; i < 32; i += 8) {
        int c = c0 + i;
        tile[i][threadIdx.x] = (c < C) ? X[(long)b * bsx + (long)c * Nn + n0 + threadIdx.x] : 0.f;
    }
    __syncthreads();
    for (int i = threadIdx.y; i < 32; i += 8) {
        int n = n0 + i, c = c0 + threadIdx.x;
        if (c < C) XT[((long)b * Nn + n) * C + c] = tile[threadIdx.x][i];
    }
}

// Wqk[i][j] = sum_e wk[e][i] * wq[e][j]
__global__ void k_wqk(const float* __restrict__ wk, const float* __restrict__ wq,
                      float* __restrict__ out, int C) {
    int j = blockIdx.x * 16 + threadIdx.x;
    int i = blockIdx.y * 16 + threadIdx.y;
    if (i >= C || j >= C) return;
    float a = 0.f;
    for (int e = 0; e < C; e++) a += wk[e * C + i] * wq[e * C + j];
    out[i * C + j] = a;
}

// Wcv[i][j] = sum_v wc[i][v] * wv[v][j]
__global__ void k_wcv(const float* __restrict__ wc, const float* __restrict__ wv,
                      float* __restrict__ out, int C) {
    int j = blockIdx.x * 16 + threadIdx.x;
    int i = blockIdx.y * 16 + threadIdx.y;
    if (i >= C || j >= C) return;
    float a = 0.f;
    for (int v = 0; v < C; v++) a += wc[i * C + v] * wv[v * C + j];
    out[i * C + j] = a;
}

// attention gather/softmax: one warp per point, 32 points per block
__global__ void k_attn2(const float* __restrict__ XT, const float* __restrict__ QKT,
                        int C, const int* __restrict__ idx,
                        float* __restrict__ M, long bsm) {
    __shared__ float s_m[128][33];
    const unsigned FULL = 0xffffffffu;
    int w = threadIdx.x >> 5, lane = threadIdx.x & 31;
    int pt = blockIdx.x * 32 + w;
    int b = pt / Nn;
    int n0 = (blockIdx.x & 63) * 32;
    int NR = (C + 31) >> 5;

    float qk[4], f[4];
    const float* qrow = QKT + (long)pt * C;
    const float* frow = XT + (long)pt * C;
    #pragma unroll
    for (int r = 0; r < 4; r++) {
        int c = lane + 32 * r;
        bool ok = (r < NR) && (c < C);
        qk[r] = ok ? qrow[c] : 0.f;
        f[r]  = ok ? frow[c] : 0.f;
    }
    const int* ip = idx + (long)pt * Kk;

    float myscore = 0.f;
    for (int j = 0; j < Kk; j++) {
        int ij = ip[j];
        const float* nrow = XT + ((long)b * Nn + ij) * C;
        float p = 0.f;
        #pragma unroll
        for (int r = 0; r < 4; r++) {
            int c = lane + 32 * r;
            if (r < NR && c < C) p += qk[r] * nrow[c];
        }
        #pragma unroll
        for (int off = 16; off > 0; off >>= 1) p += __shfl_xor_sync(FULL, p, off);
        if (lane == j) myscore = p;
    }
    float scale = rsqrtf((float)C);
    float val = (lane < Kk) ? myscore * scale : -3.0e38f;
    float mx = val;
    #pragma unroll
    for (int off = 16; off > 0; off >>= 1) mx = fmaxf(mx, __shfl_xor_sync(FULL, mx, off));
    float e = (lane < Kk) ? expf(val - mx) : 0.f;
    float sm = e;
    #pragma unroll
    for (int off = 16; off > 0; off >>= 1) sm += __shfl_xor_sync(FULL, sm, off);
    float wme = e / sm;

    float m[4] = {0.f, 0.f, 0.f, 0.f};
    for (int j = 0; j < Kk; j++) {
        float wj = __shfl_sync(FULL, wme, j);
        int ij = ip[j];
        const float* nrow = XT + ((long)b * Nn + ij) * C;
        #pragma unroll
        for (int r = 0; r < 4; r++) {
            int c = lane + 32 * r;
            if (r < NR && c < C) m[r] += wj * nrow[c];
        }
    }
    #pragma unroll
    for (int r = 0; r < 4; r++) m[r] -= f[r];

    #pragma unroll
    for (int r = 0; r < 4; r++) {
        int c = lane + 32 * r;
        if (r < NR && c < C) s_m[c][w] = m[r];
    }
    __syncthreads();
    int t = threadIdx.x;
    for (int e2 = t; e2 < C * 32; e2 += 1024) {
        int c = e2 >> 5, p2 = e2 & 31;
        M[(long)b * bsm + (long)c * Nn + n0 + p2] = s_m[c][p2];
    }
}

// per-channel batch stats over (B,N)
__global__ void k_bnstats(const float* __restrict__ Y, long bsy,
                          float* __restrict__ mean, float* __restrict__ rstd) {
    int o = blockIdx.x;
    int t = threadIdx.x;
    float s1 = 0.f, s2 = 0.f;
    for (int i = t; i < Bb * Nn; i += 256) {
        int b = i / Nn, n = i % Nn;
        float v = Y[(long)b * bsy + (long)o * Nn + n];
        s1 += v; s2 += v * v;
    }
    __shared__ float r1[256], r2[256];
    r1[t] = s1; r2[t] = s2;
    __syncthreads();
    for (int off = 128; off > 0; off >>= 1) {
        if (t < off) { r1[t] += r1[t + off]; r2[t] += r2[t + off]; }
        __syncthreads();
    }
    if (t == 0) {
        float m = r1[0] / (float)(Bb * Nn);
        float v = r2[0] / (float)(Bb * Nn) - m * m;
        mean[o] = m;
        rstd[o] = rsqrtf(v + 1e-5f);
    }
}

__global__ void k_bnapply(float* __restrict__ Y, long bsy, int O,
                          const float* __restrict__ mean, const float* __restrict__ rstd) {
    long total = (long)Bb * O * Nn;
    for (long i = (long)blockIdx.x * blockDim.x + threadIdx.x; i < total;
         i += (long)gridDim.x * blockDim.x) {
        int n = (int)(i % Nn);
        long bo = i / Nn;
        int o = (int)(bo % O);
        int b = (int)(bo / O);
        float* p = Y + (long)b * bsy + (long)o * Nn + n;
        float v = (*p - mean[o]) * rstd[o];
        *p = v >= 0.f ? v : 0.2f * v;
    }
}

__global__ void k_copy(const float* __restrict__ X, long bsx,
                       float* __restrict__ D, long bsd, int C) {
    long total = (long)Bb * C * Nn;
    for (long i = (long)blockIdx.x * blockDim.x + threadIdx.x; i < total;
         i += (long)gridDim.x * blockDim.x) {
        int n = (int)(i % Nn);
        long bc = i / Nn;
        int c = (int)(bc % C);
        int b = (int)(bc / C);
        D[(long)b * bsd + (long)c * Nn + n] = X[(long)b * bsx + (long)c * Nn + n];
    }
}

__global__ void k_pool(const float* __restrict__ X5, float* __restrict__ p) {
    int bc = blockIdx.x;
    int b = bc / 1024, c = bc % 1024;
    const float* xp = X5 + ((long)b * 1024 + c) * Nn;
    int t = threadIdx.x;
    float mx = -3e38f, sm = 0.f;
    for (int n = t; n < Nn; n += 256) { float v = xp[n]; mx = fmaxf(mx, v); sm += v; }
    __shared__ float smx[256], ssm[256];
    smx[t] = mx; ssm[t] = sm;
    __syncthreads();
    for (int off = 128; off > 0; off >>= 1) {
        if (t < off) { smx[t] = fmaxf(smx[t], smx[t + off]); ssm[t] += ssm[t + off]; }
        __syncthreads();
    }
    if (t == 0) {
        p[b * 2048 + c]        = smx[0];
        p[b * 2048 + 1024 + c] = ssm[0] / (float)Nn;
    }
}

__global__ void k_linear(const float* __restrict__ in, const float* __restrict__ W,
                         const float* __restrict__ bias, float* __restrict__ out,
                         int I, int O) {
    int w = (blockIdx.x * blockDim.x + threadIdx.x) >> 5;
    int lane = threadIdx.x & 31;
    if (w >= Bb * O) return;
    int b = w / O, o = w % O;
    const float* ip = in + (long)b * I;
    const float* wp = W + (long)o * I;
    float a = 0.f;
    for (int i = lane; i < I; i += 32) a += ip[i] * wp[i];
    for (int off = 16; off > 0; off >>= 1) a += __shfl_down_sync(0xffffffffu, a, off);
    if (lane == 0) out[w] = a + bias[o];
}

__global__ void k_bnf(float* __restrict__ Y, int O) {
    int o = blockIdx.x * blockDim.x + threadIdx.x;
    if (o >= O) return;
    float s1 = 0.f, s2 = 0.f;
    for (int b = 0; b < Bb; b++) { float v = Y[b * O + o]; s1 += v; s2 += v * v; }
    float m = s1 / (float)Bb;
    float v = s2 / (float)Bb - m * m;
    float r = rsqrtf(v + 1e-5f);
    for (int b = 0; b < Bb; b++) {
        float u = (Y[b * O + o] - m) * r;
        Y[b * O + o] = u >= 0.f ? u : 0.2f * u;
    }
}

// ---------------- host orchestration ----------------------------------------

static void gemm_h(const float* A, long bsa, int lda, const float* X, long bsx,
                   int C, int O, float* Y, long bsy, const float* sq, int dist) {
    if (O % 128 == 0) {
        dim3 g(Nn / 128, O / 128, Bb);
        k_gemm<128, 8><<<g, 256>>>(A, bsa, lda, X, bsx, C, O, Y, bsy, sq, dist);
    } else {
        dim3 g(Nn / 128, (O + 63) / 64, Bb);
        k_gemm<64, 4><<<g, 256>>>(A, bsa, lda, X, bsx, C, O, Y, bsy, sq, dist);
    }
}

struct Scratch {
    float *pd, *sq, *att, *qk, *xt, *qkt, *wqk, *wcv, *h, *xc, *x5, *mean, *rstd, *p, *f1, *f2;
    int* idx;
};

static void conv_bn_h(const float* X, long bsx, int C, const float* W, int O,
                      float* Y, long bsy, float* mean, float* rstd) {
    gemm_h(W, 0, C, X, bsx, C, O, Y, bsy, nullptr, 0);
    k_bnstats<<<O, 256>>>(Y, bsy, mean, rstd);
    long total = (long)Bb * O * Nn;
    k_bnapply<<<(int)((total + 255) / 256), 256>>>(Y, bsy, O, mean, rstd);
}

static void self_att_h(const float* X, long bsx, int C,
                       const float* wq, const float* wk, const float* wv, const float* wc,
                       float* H, long bsh, const Scratch& S) {
    k_sqnorm<<<(Bb * Nn + 255) / 256, 256>>>(X, bsx, C, S.sq);

    // transpose X -> XT [B,N,C]  (needed by dist-GEMM A-operand and attn2)
    dim3 tg(Nn / 32, (C + 31) / 32, Bb);
    k_transpose<<<tg, dim3(32, 8)>>>(X, bsx, C, S.xt);

    // dist = GEMM(A=XT, X) with dist epilogue
    gemm_h(S.xt, (long)Nn * C, C, X, bsx, C, Nn, S.pd, (long)Nn * Nn, S.sq, 1);
    k_topk<<<Bb * Nn, 128>>>(S.pd, S.idx);

    // Wqk = wk^T wq ; QK = Wqk @ X ; transpose -> QKT
    dim3 sg((C + 15) / 16, (C + 15) / 16);
    k_wqk<<<sg, dim3(16, 16)>>>(wk, wq, S.wqk, C);
    gemm_h(S.wqk, 0, C, X, bsx, C, C, S.qk, (long)C * Nn, nullptr, 0);
    k_transpose<<<tg, dim3(32, 8)>>>(S.qk, (long)C * Nn, C, S.qkt);

    // gather + softmax + weighted diff -> M
    k_attn2<<<Bb * Nn / 32, 1024>>>(S.xt, S.qkt, C, S.idx, S.att, (long)C * Nn);

    // res = conv_bn(Wcv @ M)
    k_wcv<<<sg, dim3(16, 16)>>>(wc, wv, S.wcv, C);
    conv_bn_h(S.att, (long)C * Nn, C, S.wcv, C, H, bsh, S.mean, S.rstd);

    // concat raw x into channels [C, 2C)
    long total = (long)Bb * C * Nn;
    k_copy<<<(int)((total + 255) / 256), 256>>>(X, bsx, H + (long)C * Nn, bsh, C);
}

extern "C" void kernel_launch(void* const* d_in, const int* in_sizes, int n_in,
                              void* d_out, int out_size) {
    const float* x = (const float*)d_in[0];
    const float* sa_wq[4] = {(const float*)d_in[1],  (const float*)d_in[5],
                             (const float*)d_in[9],  (const float*)d_in[13]};
    const float* sa_wk[4] = {(const float*)d_in[2],  (const float*)d_in[6],
                             (const float*)d_in[10], (const float*)d_in[14]};
    const float* sa_wv[4] = {(const float*)d_in[3],  (const float*)d_in[7],
                             (const float*)d_in[11], (const float*)d_in[15]};
    const float* sa_wc[4] = {(const float*)d_in[4],  (const float*)d_in[8],
                             (const float*)d_in[12], (const float*)d_in[16]};
    const float* conv1_w = (const float*)d_in[17];
    const float* conv2_w = (const float*)d_in[18];
    const float* conv3_w = (const float*)d_in[19];
    const float* conv4_w = (const float*)d_in[20];
    const float* conv5_w = (const float*)d_in[21];
    const float* lin1_w = (const float*)d_in[22];
    const float* lin1_b = (const float*)d_in[23];
    const float* lin2_w = (const float*)d_in[24];
    const float* lin2_b = (const float*)d_in[25];
    const float* lin3_w = (const float*)d_in[26];
    const float* lin3_b = (const float*)d_in[27];

    Scratch S;
    cudaGetSymbolAddress((void**)&S.pd,   g_pd);
    cudaGetSymbolAddress((void**)&S.idx,  g_idx);
    cudaGetSymbolAddress((void**)&S.sq,   g_sq);
    cudaGetSymbolAddress((void**)&S.h,    g_h);
    cudaGetSymbolAddress((void**)&S.att,  g_att);
    cudaGetSymbolAddress((void**)&S.qk,   g_qk);
    cudaGetSymbolAddress((void**)&S.xt,   g_xt);
    cudaGetSymbolAddress((void**)&S.qkt,  g_qkt);
    cudaGetSymbolAddress((void**)&S.wqk,  g_wqk);
    cudaGetSymbolAddress((void**)&S.wcv,  g_wcv);
    cudaGetSymbolAddress((void**)&S.xc,   g_xc);
    cudaGetSymbolAddress((void**)&S.x5,   g_x5);
    cudaGetSymbolAddress((void**)&S.mean, g_mean);
    cudaGetSymbolAddress((void**)&S.rstd, g_rstd);
    cudaGetSymbolAddress((void**)&S.p,    g_p);
    cudaGetSymbolAddress((void**)&S.f1,   g_f1);
    cudaGetSymbolAddress((void**)&S.f2,   g_f2);

    const long bxc = (long)512 * Nn;

    self_att_h(x, (long)3 * Nn, 3, sa_wq[0], sa_wk[0], sa_wv[0], sa_wc[0],
               S.h, (long)6 * Nn, S);
    conv_bn_h(S.h, (long)6 * Nn, 6, conv1_w, 64, S.xc, bxc, S.mean, S.rstd);

    self_att_h(S.xc, bxc, 64, sa_wq[1], sa_wk[1], sa_wv[1], sa_wc[1],
               S.h, (long)128 * Nn, S);
    conv_bn_h(S.h, (long)128 * Nn, 128, conv2_w, 64, S.xc + (long)64 * Nn, bxc, S.mean, S.rstd);

    self_att_h(S.xc + (long)64 * Nn, bxc, 64, sa_wq[2], sa_wk[2], sa_wv[2], sa_wc[2],
               S.h, (long)128 * Nn, S);
    conv_bn_h(S.h, (long)128 * Nn, 128, conv3_w, 128, S.xc + (long)128 * Nn, bxc, S.mean, S.rstd);

    self_att_h(S.xc + (long)128 * Nn, bxc, 128, sa_wq[3], sa_wk[3], sa_wv[3], sa_wc[3],
               S.h, (long)256 * Nn, S);
    conv_bn_h(S.h, (long)256 * Nn, 256, conv4_w, 256, S.xc + (long)256 * Nn, bxc, S.mean, S.rstd);

    conv_bn_h(S.xc, bxc, 512, conv5_w, 1024, S.x5, (long)1024 * Nn, S.mean, S.rstd);

    k_pool<<<Bb * 1024, 256>>>(S.x5, S.p);

    k_linear<<<(Bb * 512 + 7) / 8, 256>>>(S.p, lin1_w, lin1_b, S.f1, 2048, 512);
    k_bnf<<<2, 256>>>(S.f1, 512);
    k_linear<<<(Bb * 256 + 7) / 8, 256>>>(S.f1, lin2_w, lin2_b, S.f2, 512, 256);
    k_bnf<<<1, 256>>>(S.f2, 256);
    k_linear<<<(Bb * 40 + 7) / 8, 256>>>(S.f2, lin3_w, lin3_b, (float*)d_out, 256, 40);
}